// round 16
// baseline (speedup 1.0000x reference)
#include <cuda_runtime.h>

#define H_LR 512
#define W_LR 512
#define H_HR 2048
#define W_HR 2048
#define PLANES 12
#define EPS_F 0.01f
#define SCALE_F (511.0f / 2047.0f)

#define CHUNK 3
#define NCHUNK (PLANES / CHUNK)

// Scratch for mean_A / mean_b at low resolution (alloc-free: __device__ globals)
__device__ float g_meanA[PLANES * H_LR * W_LR];
__device__ float g_meanB[PLANES * H_LR * W_LR];

// Fast reciprocal on the FMA pipe (no MUFU), valid for d in [~1e-2, ~1].
__device__ __forceinline__ float fast_rcp(float d) {
    float r = __uint_as_float(0x7EF311C3u - __float_as_uint(d));
    r = r * fmaf(-d, r, 2.0f);
    r = r * fmaf(-d, r, 2.0f);
    return r;
}

// ---------------------------------------------------------------------------
// k1: warp-streaming A/b + double box filter. No smem, no barriers.
// Lane owns a column; rows stream with register rings:
//   hsum(row)  : horizontal 3-taps of x,y,xy,xx  (shuffle neighbors)
//   A,b(row)   : vertical 3-sum of hsums + rcp   (thread-local)
//   hA,hB(row) : horizontal 3-tap of A,b         (shuffle neighbors)
//   mean(row)  : vertical 3-sum of hA,hB -> store
// Warp covers 32 input cols, outputs the middle 30. Edge/halo lanes
// (L==0, L==31, or at image edges) load their 3 taps directly (clamped),
// which makes replication padding exact at the image borders.
// Row replication: x rows are loaded clamped (=> A(0)/A(511) exact);
// A(-1):=A(0) and A(512):=A(511) handled by ring-slot copies.
// Strip = 32 output rows => 36 streamed rows (unroll-by-3 ring).
// ---------------------------------------------------------------------------
__global__ __launch_bounds__(256)
void k1_ab_mean(const float* __restrict__ x, const float* __restrict__ y, int plane_base) {
    const int w = threadIdx.x >> 5;
    const int L = threadIdx.x & 31;
    const int col0 = blockIdx.x * 240 + 30 * w;   // first output col of this warp
    if (col0 > 511) return;                        // idle warps of the ragged block

    const int plane = plane_base + blockIdx.z;
    const int R0 = blockIdx.y * 32;
    const int rs = R0 - 2;
    const bool topStrip = (R0 == 0);

    const int c_in = col0 + L - 1;                 // lane's column (may be -1..543)
    const int c_eff = min(max(c_in, 0), W_LR - 1);
    const int cl = max(c_eff - 1, 0);
    const int cr = min(c_eff + 1, W_LR - 1);
    const bool direct = (L == 0) || (L == 31) || (c_in <= 0) || (c_in >= W_LR - 1);
    const bool valid_out = (L >= 1) && (L <= 30) && (c_in <= W_LR - 1);

    const float* __restrict__ xp = x + (size_t)plane * (H_LR * W_LR);
    const float* __restrict__ yp = y + (size_t)plane * (H_LR * W_LR);
    float* __restrict__ outA = g_meanA + (size_t)plane * (H_LR * W_LR) + c_eff;
    float* __restrict__ outB = g_meanB + (size_t)plane * (H_LR * W_LR) + c_eff;

    const float inv9 = 1.0f / 9.0f;
    float hx[3], hy[3], hxy[3], hxx[3];
    float hA[3], hB[3];

    for (int g = 0; g < 12; g++) {
        #pragma unroll
        for (int s = 0; s < 3; s++) {
            const int it = g * 3 + s;
            const int r = rs + it;
            const int rr = min(max(r, 0), H_LR - 1);
            const float* xrow = xp + rr * W_LR;
            const float* yrow = yp + rr * W_LR;

            // horizontal taps: own col + shuffle neighbors (direct lanes reload)
            float xc = __ldg(xrow + c_eff);
            float yc = __ldg(yrow + c_eff);
            float xl = __shfl_up_sync(0xffffffffu, xc, 1);
            float xr2 = __shfl_down_sync(0xffffffffu, xc, 1);
            float yl = __shfl_up_sync(0xffffffffu, yc, 1);
            float yr2 = __shfl_down_sync(0xffffffffu, yc, 1);
            if (direct) {
                xl = __ldg(xrow + cl); xr2 = __ldg(xrow + cr);
                yl = __ldg(yrow + cl); yr2 = __ldg(yrow + cr);
            }
            hx[s]  = xl + xc + xr2;
            hy[s]  = yl + yc + yr2;
            hxy[s] = fmaf(xl, yl, fmaf(xc, yc, xr2 * yr2));
            hxx[s] = fmaf(xl, xl, fmaf(xc, xc, xr2 * xr2));

            // A,b at row a = r-1 (vertical sums are symmetric over the ring)
            if (it >= 2) {
                float sxs  = hx[0] + hx[1] + hx[2];
                float sys  = hy[0] + hy[1] + hy[2];
                float sxys = hxy[0] + hxy[1] + hxy[2];
                float sxxs = hxx[0] + hxx[1] + hxx[2];
                float mx = sxs * inv9, my = sys * inv9;
                float cov = fmaf(-mx, my, sxys * inv9);
                float var = fmaf(-mx, mx, sxxs * inv9);
                float A_ = cov * fast_rcp(var + EPS_F);
                float B_ = fmaf(-A_, mx, my);

                float Au = __shfl_up_sync(0xffffffffu, A_, 1);
                float Ad = __shfl_down_sync(0xffffffffu, A_, 1);
                float Bu = __shfl_up_sync(0xffffffffu, B_, 1);
                float Bd = __shfl_down_sync(0xffffffffu, B_, 1);
                float hAv = Au + A_ + Ad;
                float hBv = Bu + B_ + Bd;

                const int a = r - 1;
                if (a >= H_LR) {                    // A(512) := A(511)
                    hAv = hA[(s + 1) % 3];
                    hBv = hB[(s + 1) % 3];
                }
                hA[(s + 2) % 3] = hAv;
                hB[(s + 2) % 3] = hBv;
                if (topStrip && a == 0) {           // A(-1) := A(0)
                    hA[(s + 1) % 3] = hAv;
                    hB[(s + 1) % 3] = hBv;
                }
            }

            // mean_A/mean_b at row j = r-2
            if (it >= 4) {
                float mA = (hA[0] + hA[1] + hA[2]) * inv9;
                float mB = (hB[0] + hB[1] + hB[2]) * inv9;
                if (valid_out) {
                    outA[(r - 2) * W_LR] = mA;
                    outB[(r - 2) * W_LR] = mB;
                }
            }
        }
    }
}

// Kernel 2 (unchanged, round-15): one block per output row; staged
// vertically-lerped Ac/Bc in SMEM; 8 px/thread, select-free piecewise lerp;
// streaming loads/stores for the zero-reuse hi-res tensors.
__global__ __launch_bounds__(256)
void k2_upsample_apply(const float* __restrict__ xhr, float* __restrict__ out, int plane_base) {
    __shared__ float sAc[W_LR];
    __shared__ float sBc[W_LR];

    const int plane = plane_base + blockIdx.y;
    const int oy = blockIdx.x;
    const int t = threadIdx.x;

    float posy = (float)oy * SCALE_F;
    int iy0 = (int)posy;
    float tyf = posy - (float)iy0;
    int iy1 = min(iy0 + 1, H_LR - 1);

    const size_t pl = (size_t)plane * (H_LR * W_LR);
    if (t < 128) {
        const float4* r0 = (const float4*)(g_meanA + pl + iy0 * W_LR);
        const float4* r1 = (const float4*)(g_meanA + pl + iy1 * W_LR);
        float4 a0 = r0[t], a1 = r1[t];
        float4 ac;
        ac.x = fmaf(tyf, a1.x - a0.x, a0.x);
        ac.y = fmaf(tyf, a1.y - a0.y, a0.y);
        ac.z = fmaf(tyf, a1.z - a0.z, a0.z);
        ac.w = fmaf(tyf, a1.w - a0.w, a0.w);
        ((float4*)sAc)[t] = ac;
    } else {
        int u = t - 128;
        const float4* r0 = (const float4*)(g_meanB + pl + iy0 * W_LR);
        const float4* r1 = (const float4*)(g_meanB + pl + iy1 * W_LR);
        float4 b0 = r0[u], b1 = r1[u];
        float4 bc;
        bc.x = fmaf(tyf, b1.x - b0.x, b0.x);
        bc.y = fmaf(tyf, b1.y - b0.y, b0.y);
        bc.z = fmaf(tyf, b1.z - b0.z, b0.z);
        bc.w = fmaf(tyf, b1.w - b0.w, b0.w);
        ((float4*)sBc)[u] = bc;
    }

    const size_t base = (size_t)plane * (H_HR * W_HR) + (size_t)oy * W_HR;
    const float4* __restrict__ xin4 = (const float4*)(xhr + base);
    float4* __restrict__ out4 = (float4*)(out + base);

    const int q0 = t * 2;
    float4 xv0 = __ldcs(xin4 + q0);
    float4 xv1 = __ldcs(xin4 + q0 + 1);

    __syncthreads();

    const int ox0 = t * 8;
    float posx0 = (float)ox0 * SCALE_F;
    int jb = (int)posx0;
    float f0 = posx0 - (float)jb;

    int j3 = min(jb + 3, W_LR - 1);
    float A0 = sAc[jb], A1 = sAc[jb + 1], A2 = sAc[jb + 2], A3 = sAc[j3];
    float B0 = sBc[jb], B1 = sBc[jb + 1], B2 = sBc[jb + 2], B3 = sBc[j3];
    float DA0 = A1 - A0, DA1 = A2 - A1, DA2 = A3 - A2;
    float DB0 = B1 - B0, DB1 = B2 - B1, DB2 = B3 - B2;

    float xin[8] = {xv0.x, xv0.y, xv0.z, xv0.w, xv1.x, xv1.y, xv1.z, xv1.w};
    float res[8];
    #pragma unroll
    for (int k = 0; k < 8; k++) {
        float p = fmaf((float)k, SCALE_F, f0);
        float t0 = __saturatef(p);
        float t1 = __saturatef(p - 1.0f);
        float t2 = __saturatef(p - 2.0f);
        float aV = fmaf(DA2, t2, fmaf(DA1, t1, fmaf(DA0, t0, A0)));
        float bV = fmaf(DB2, t2, fmaf(DB1, t1, fmaf(DB0, t0, B0)));
        float r = fmaf(aV, xin[k], bV);
        res[k] = fminf(fmaxf(r, 0.0f), 255.0f);
    }

    __stcs(out4 + q0,     make_float4(res[0], res[1], res[2], res[3]));
    __stcs(out4 + q0 + 1, make_float4(res[4], res[5], res[6], res[7]));
}

// Stream + events at static-init time (timing-disabled; no device allocs).
// Fork k1 chunks onto a side stream during capture: k1(chunk c+1..) overlaps
// k2(chunk 0..c). With the lean k1, combined issue demand now fits.
namespace {
struct GfRes {
    cudaStream_t s1 = nullptr;
    cudaEvent_t evFork = nullptr;
    cudaEvent_t evC[NCHUNK] = {};
    GfRes() {
        cudaStreamCreateWithFlags(&s1, cudaStreamNonBlocking);
        cudaEventCreateWithFlags(&evFork, cudaEventDisableTiming);
        for (int c = 0; c < NCHUNK; c++)
            cudaEventCreateWithFlags(&evC[c], cudaEventDisableTiming);
    }
};
GfRes g_res;
}

extern "C" void kernel_launch(void* const* d_in, const int* in_sizes, int n_in,
                              void* d_out, int out_size) {
    const float* x_lr = (const float*)d_in[0];
    const float* y_lr = (const float*)d_in[1];
    const float* x_hr = (const float*)d_in[2];
    float* out = (float*)d_out;

    cudaEventRecord(g_res.evFork, 0);
    cudaStreamWaitEvent(g_res.s1, g_res.evFork, 0);

    dim3 g1(3, 16, CHUNK);                  // 3 col-blocks x 16 strips x CHUNK planes
    for (int c = 0; c < NCHUNK; c++) {
        k1_ab_mean<<<g1, 256, 0, g_res.s1>>>(x_lr, y_lr, c * CHUNK);
        cudaEventRecord(g_res.evC[c], g_res.s1);
    }

    dim3 g2(H_HR, CHUNK);
    for (int c = 0; c < NCHUNK; c++) {
        cudaStreamWaitEvent((cudaStream_t)0, g_res.evC[c], 0);
        k2_upsample_apply<<<g2, 256>>>(x_hr, out, c * CHUNK);
    }
}

// round 17
// speedup vs baseline: 1.4451x; 1.4451x over previous
#include <cuda_runtime.h>

#define H_LR 512
#define W_LR 512
#define H_HR 2048
#define W_HR 2048
#define PLANES 12
#define EPS_F 0.01f
#define SCALE_F (511.0f / 2047.0f)

#define CHUNK 3
#define NCHUNK (PLANES / CHUNK)
#define STRIP 8                       // output rows per k1 block (12 streamed)

// Scratch for mean_A / mean_b at low resolution (alloc-free: __device__ globals)
__device__ float g_meanA[PLANES * H_LR * W_LR];
__device__ float g_meanB[PLANES * H_LR * W_LR];

// Fast reciprocal on the FMA pipe (no MUFU), valid for d in [~1e-2, ~1].
__device__ __forceinline__ float fast_rcp(float d) {
    float r = __uint_as_float(0x7EF311C3u - __float_as_uint(d));
    r = r * fmaf(-d, r, 2.0f);
    r = r * fmaf(-d, r, 2.0f);
    return r;
}

// ---------------------------------------------------------------------------
// k1: warp-streaming A/b + double box filter. No smem, no barriers.
// (Validated numerically in round 16; reshaped here for parallelism.)
// Lane owns a column; rows stream with register rings:
//   hsum(row)  : horizontal 3-taps of x,y,xy,xx  (shuffle neighbors)
//   A,b(row)   : vertical 3-sum of hsums + rcp   (thread-local)
//   hA,hB(row) : horizontal 3-tap of A,b         (shuffle neighbors)
//   mean(row)  : vertical 3-sum of hA,hB -> store
// Warp covers 32 input cols, outputs the middle 30; edge/halo lanes load
// their 3 taps directly (clamped) making border replication exact.
// Row replication: clamped row loads (=> A(0)/A(511) exact); A(-1):=A(0),
// A(512):=A(511) via ring-slot copies.
// Strip = 8 output rows => 12 streamed rows per block.
// ---------------------------------------------------------------------------
__global__ __launch_bounds__(256)
void k1_ab_mean(const float* __restrict__ x, const float* __restrict__ y, int plane_base) {
    const int w = threadIdx.x >> 5;
    const int L = threadIdx.x & 31;
    const int col0 = blockIdx.x * 240 + 30 * w;   // first output col of this warp
    if (col0 > 511) return;                        // idle warps of the ragged block

    const int plane = plane_base + blockIdx.z;
    const int R0 = blockIdx.y * STRIP;
    const int rs = R0 - 2;
    const bool topStrip = (R0 == 0);

    const int c_in = col0 + L - 1;                 // lane's column (may be -1..543)
    const int c_eff = min(max(c_in, 0), W_LR - 1);
    const int cl = max(c_eff - 1, 0);
    const int cr = min(c_eff + 1, W_LR - 1);
    const bool direct = (L == 0) || (L == 31) || (c_in <= 0) || (c_in >= W_LR - 1);
    const bool valid_out = (L >= 1) && (L <= 30) && (c_in <= W_LR - 1);

    const float* __restrict__ xp = x + (size_t)plane * (H_LR * W_LR);
    const float* __restrict__ yp = y + (size_t)plane * (H_LR * W_LR);
    float* __restrict__ outA = g_meanA + (size_t)plane * (H_LR * W_LR) + c_eff;
    float* __restrict__ outB = g_meanB + (size_t)plane * (H_LR * W_LR) + c_eff;

    const float inv9 = 1.0f / 9.0f;
    float hx[3], hy[3], hxy[3], hxx[3];
    float hA[3], hB[3];

    #pragma unroll
    for (int g = 0; g < (STRIP + 4) / 3; g++) {
        #pragma unroll
        for (int s = 0; s < 3; s++) {
            const int it = g * 3 + s;
            const int r = rs + it;
            const int rr = min(max(r, 0), H_LR - 1);
            const float* xrow = xp + rr * W_LR;
            const float* yrow = yp + rr * W_LR;

            // horizontal taps: own col + shuffle neighbors (direct lanes reload)
            float xc = __ldg(xrow + c_eff);
            float yc = __ldg(yrow + c_eff);
            float xl = __shfl_up_sync(0xffffffffu, xc, 1);
            float xr2 = __shfl_down_sync(0xffffffffu, xc, 1);
            float yl = __shfl_up_sync(0xffffffffu, yc, 1);
            float yr2 = __shfl_down_sync(0xffffffffu, yc, 1);
            if (direct) {
                xl = __ldg(xrow + cl); xr2 = __ldg(xrow + cr);
                yl = __ldg(yrow + cl); yr2 = __ldg(yrow + cr);
            }
            hx[s]  = xl + xc + xr2;
            hy[s]  = yl + yc + yr2;
            hxy[s] = fmaf(xl, yl, fmaf(xc, yc, xr2 * yr2));
            hxx[s] = fmaf(xl, xl, fmaf(xc, xc, xr2 * xr2));

            // A,b at row a = r-1 (vertical sums symmetric over the ring)
            if (it >= 2) {
                float sxs  = hx[0] + hx[1] + hx[2];
                float sys  = hy[0] + hy[1] + hy[2];
                float sxys = hxy[0] + hxy[1] + hxy[2];
                float sxxs = hxx[0] + hxx[1] + hxx[2];
                float mx = sxs * inv9, my = sys * inv9;
                float cov = fmaf(-mx, my, sxys * inv9);
                float var = fmaf(-mx, mx, sxxs * inv9);
                float A_ = cov * fast_rcp(var + EPS_F);
                float B_ = fmaf(-A_, mx, my);

                float Au = __shfl_up_sync(0xffffffffu, A_, 1);
                float Ad = __shfl_down_sync(0xffffffffu, A_, 1);
                float Bu = __shfl_up_sync(0xffffffffu, B_, 1);
                float Bd = __shfl_down_sync(0xffffffffu, B_, 1);
                float hAv = Au + A_ + Ad;
                float hBv = Bu + B_ + Bd;

                const int a = r - 1;
                if (a >= H_LR) {                    // A(512) := A(511)
                    hAv = hA[(s + 1) % 3];
                    hBv = hB[(s + 1) % 3];
                }
                hA[(s + 2) % 3] = hAv;
                hB[(s + 2) % 3] = hBv;
                if (topStrip && a == 0) {           // A(-1) := A(0)
                    hA[(s + 1) % 3] = hAv;
                    hB[(s + 1) % 3] = hBv;
                }
            }

            // mean_A/mean_b at row j = r-2
            if (it >= 4) {
                float mA = (hA[0] + hA[1] + hA[2]) * inv9;
                float mB = (hB[0] + hB[1] + hB[2]) * inv9;
                if (valid_out) {
                    outA[(r - 2) * W_LR] = mA;
                    outB[(r - 2) * W_LR] = mB;
                }
            }
        }
    }
}

// Kernel 2 (unchanged): one block per output row; staged vertically-lerped
// Ac/Bc in SMEM; 8 px/thread, select-free piecewise lerp; streaming
// loads/stores for the zero-reuse hi-res tensors.
__global__ __launch_bounds__(256)
void k2_upsample_apply(const float* __restrict__ xhr, float* __restrict__ out, int plane_base) {
    __shared__ float sAc[W_LR];
    __shared__ float sBc[W_LR];

    const int plane = plane_base + blockIdx.y;
    const int oy = blockIdx.x;
    const int t = threadIdx.x;

    float posy = (float)oy * SCALE_F;
    int iy0 = (int)posy;
    float tyf = posy - (float)iy0;
    int iy1 = min(iy0 + 1, H_LR - 1);

    const size_t pl = (size_t)plane * (H_LR * W_LR);
    if (t < 128) {
        const float4* r0 = (const float4*)(g_meanA + pl + iy0 * W_LR);
        const float4* r1 = (const float4*)(g_meanA + pl + iy1 * W_LR);
        float4 a0 = r0[t], a1 = r1[t];
        float4 ac;
        ac.x = fmaf(tyf, a1.x - a0.x, a0.x);
        ac.y = fmaf(tyf, a1.y - a0.y, a0.y);
        ac.z = fmaf(tyf, a1.z - a0.z, a0.z);
        ac.w = fmaf(tyf, a1.w - a0.w, a0.w);
        ((float4*)sAc)[t] = ac;
    } else {
        int u = t - 128;
        const float4* r0 = (const float4*)(g_meanB + pl + iy0 * W_LR);
        const float4* r1 = (const float4*)(g_meanB + pl + iy1 * W_LR);
        float4 b0 = r0[u], b1 = r1[u];
        float4 bc;
        bc.x = fmaf(tyf, b1.x - b0.x, b0.x);
        bc.y = fmaf(tyf, b1.y - b0.y, b0.y);
        bc.z = fmaf(tyf, b1.z - b0.z, b0.z);
        bc.w = fmaf(tyf, b1.w - b0.w, b0.w);
        ((float4*)sBc)[u] = bc;
    }

    const size_t base = (size_t)plane * (H_HR * W_HR) + (size_t)oy * W_HR;
    const float4* __restrict__ xin4 = (const float4*)(xhr + base);
    float4* __restrict__ out4 = (float4*)(out + base);

    const int q0 = t * 2;
    float4 xv0 = __ldcs(xin4 + q0);
    float4 xv1 = __ldcs(xin4 + q0 + 1);

    __syncthreads();

    const int ox0 = t * 8;
    float posx0 = (float)ox0 * SCALE_F;
    int jb = (int)posx0;
    float f0 = posx0 - (float)jb;

    int j3 = min(jb + 3, W_LR - 1);
    float A0 = sAc[jb], A1 = sAc[jb + 1], A2 = sAc[jb + 2], A3 = sAc[j3];
    float B0 = sBc[jb], B1 = sBc[jb + 1], B2 = sBc[jb + 2], B3 = sBc[j3];
    float DA0 = A1 - A0, DA1 = A2 - A1, DA2 = A3 - A2;
    float DB0 = B1 - B0, DB1 = B2 - B1, DB2 = B3 - B2;

    float xin[8] = {xv0.x, xv0.y, xv0.z, xv0.w, xv1.x, xv1.y, xv1.z, xv1.w};
    float res[8];
    #pragma unroll
    for (int k = 0; k < 8; k++) {
        float p = fmaf((float)k, SCALE_F, f0);
        float t0 = __saturatef(p);
        float t1 = __saturatef(p - 1.0f);
        float t2 = __saturatef(p - 2.0f);
        float aV = fmaf(DA2, t2, fmaf(DA1, t1, fmaf(DA0, t0, A0)));
        float bV = fmaf(DB2, t2, fmaf(DB1, t1, fmaf(DB0, t0, B0)));
        float r = fmaf(aV, xin[k], bV);
        res[k] = fminf(fmaxf(r, 0.0f), 255.0f);
    }

    __stcs(out4 + q0,     make_float4(res[0], res[1], res[2], res[3]));
    __stcs(out4 + q0 + 1, make_float4(res[4], res[5], res[6], res[7]));
}

// Stream + events at static-init time (timing-disabled; no device allocs).
// Fork k1 chunks onto a side stream during capture: k1(chunk c+1..) overlaps
// k2(chunk 0..c). The lean k1 leaves issue headroom for true concurrency.
namespace {
struct GfRes {
    cudaStream_t s1 = nullptr;
    cudaEvent_t evFork = nullptr;
    cudaEvent_t evC[NCHUNK] = {};
    GfRes() {
        cudaStreamCreateWithFlags(&s1, cudaStreamNonBlocking);
        cudaEventCreateWithFlags(&evFork, cudaEventDisableTiming);
        for (int c = 0; c < NCHUNK; c++)
            cudaEventCreateWithFlags(&evC[c], cudaEventDisableTiming);
    }
};
GfRes g_res;
}

extern "C" void kernel_launch(void* const* d_in, const int* in_sizes, int n_in,
                              void* d_out, int out_size) {
    const float* x_lr = (const float*)d_in[0];
    const float* y_lr = (const float*)d_in[1];
    const float* x_hr = (const float*)d_in[2];
    float* out = (float*)d_out;

    cudaEventRecord(g_res.evFork, 0);
    cudaStreamWaitEvent(g_res.s1, g_res.evFork, 0);

    dim3 g1(3, H_LR / STRIP, CHUNK);        // 3 x 64 x 3 = 576 blocks/chunk
    for (int c = 0; c < NCHUNK; c++) {
        k1_ab_mean<<<g1, 256, 0, g_res.s1>>>(x_lr, y_lr, c * CHUNK);
        cudaEventRecord(g_res.evC[c], g_res.s1);
    }

    dim3 g2(H_HR, CHUNK);
    for (int c = 0; c < NCHUNK; c++) {
        cudaStreamWaitEvent((cudaStream_t)0, g_res.evC[c], 0);
        k2_upsample_apply<<<g2, 256>>>(x_hr, out, c * CHUNK);
    }
}